// round 7
// baseline (speedup 1.0000x reference)
#include <cuda_runtime.h>
#include <cstdint>
#include <cstddef>

// ---------------------------------------------------------------------------
// MultiHeadLatentAttention: x->q, x->latent, latent->k,v, causal MHA, out proj
// B=2 S=2048 EMB=2048 H=16 D=128 LATENT=512, fp32 in/out, tf32 MMA internally.
// ---------------------------------------------------------------------------

#define EMB   2048
#define BATCH 2
#define SEQ   2048
#define NHEAD 16
#define HDIM  128
#define LAT   512
#define MTOT  (BATCH*SEQ)   // 4096

__device__ float g_q  [(size_t)MTOT*EMB];
__device__ float g_lat[(size_t)MTOT*LAT];
__device__ float g_k  [(size_t)MTOT*EMB];
__device__ float g_v  [(size_t)MTOT*EMB];
__device__ float g_ctx[(size_t)MTOT*EMB];

__device__ __forceinline__ uint32_t f2tf(float f) {
    uint32_t u;
    asm("cvt.rna.tf32.f32 %0, %1;" : "=r"(u) : "f"(f));
    return u;
}

__device__ __forceinline__ float ex2f(float x) {
    float r;
    asm("ex2.approx.ftz.f32 %0, %1;" : "=f"(r) : "f"(x));
    return r;
}

__device__ __forceinline__ void mma_tf32(float d[4],
                                         uint32_t a0, uint32_t a1, uint32_t a2, uint32_t a3,
                                         uint32_t b0, uint32_t b1) {
    asm volatile(
        "mma.sync.aligned.m16n8k8.row.col.f32.tf32.tf32.f32 "
        "{%0,%1,%2,%3}, {%4,%5,%6,%7}, {%8,%9}, {%0,%1,%2,%3};"
        : "+f"(d[0]), "+f"(d[1]), "+f"(d[2]), "+f"(d[3])
        : "r"(a0), "r"(a1), "r"(a2), "r"(a3), "r"(b0), "r"(b1));
}

__device__ __forceinline__ void cpa16(uint32_t dst, const void* src) {
    asm volatile("cp.async.cg.shared.global [%0], [%1], 16;" :: "r"(dst), "l"(src));
}
__device__ __forceinline__ void cpa_commit() {
    asm volatile("cp.async.commit_group;" ::: "memory");
}
__device__ __forceinline__ void cpa_wait0() {
    asm volatile("cp.async.wait_group 0;" ::: "memory");
}

// ---------------------------------------------------------------------------
// GEMM: C[M,N] = A[M,K] * B[N,K]^T (+bias), tf32 MMA, fp32 accum.
// B2/C2 non-null: fused second GEMM selected by blockIdx.z (same A).
// ---------------------------------------------------------------------------
#define GBM 128
#define GBN 64
#define GBK 32
#define ALD 36

__global__ __launch_bounds__(256, 2)
void gemm_tf32_nt(const float* __restrict__ A, const float* __restrict__ B1,
                  const float* __restrict__ B2,
                  const float* __restrict__ bias, float* __restrict__ C1,
                  float* __restrict__ C2,
                  int M, int N, int K, int cvt) {
    extern __shared__ uint32_t sm[];
    uint32_t* As = sm;
    uint32_t* Bs = sm + 2 * GBM * ALD;

    const float* B = (blockIdx.z == 0) ? B1 : B2;
    float*       C = (blockIdx.z == 0) ? C1 : C2;

    const int tid  = threadIdx.x;
    const int lane = tid & 31;
    const int wid  = tid >> 5;
    const int g    = lane >> 2;
    const int c    = lane & 3;
    const int wm   = (wid >> 1) * 32;
    const int wn   = (wid & 1) * 32;

    const int bm = blockIdx.y * GBM;
    const int bn = blockIdx.x * GBN;

    float acc[2][4][4];
#pragma unroll
    for (int i = 0; i < 2; i++)
#pragma unroll
        for (int j = 0; j < 4; j++)
#pragma unroll
            for (int r = 0; r < 4; r++) acc[i][j][r] = 0.f;

    const int arow = tid >> 3;
    const int acol = (tid & 7) << 2;

    const float* Ag = A + (size_t)(bm + arow) * K + acol;
    const float* Bg = B + (size_t)(bn + arow) * K + acol;

    const int ktiles = K / GBK;
    float4 ra[4], rb[2];

#pragma unroll
    for (int i = 0; i < 4; i++) ra[i] = *(const float4*)(Ag + (size_t)(i * 32) * K);
#pragma unroll
    for (int i = 0; i < 2; i++) rb[i] = *(const float4*)(Bg + (size_t)(i * 32) * K);

    auto store_tile = [&](int buf) {
        uint32_t* Ab = As + buf * GBM * ALD;
        uint32_t* Bb = Bs + buf * GBN * ALD;
#pragma unroll
        for (int i = 0; i < 4; i++) {
            uint32_t* p = Ab + (arow + i * 32) * ALD + acol;
            p[0] = f2tf(ra[i].x); p[1] = f2tf(ra[i].y);
            p[2] = f2tf(ra[i].z); p[3] = f2tf(ra[i].w);
        }
#pragma unroll
        for (int i = 0; i < 2; i++) {
            uint32_t* p = Bb + (arow + i * 32) * ALD + acol;
            p[0] = f2tf(rb[i].x); p[1] = f2tf(rb[i].y);
            p[2] = f2tf(rb[i].z); p[3] = f2tf(rb[i].w);
        }
    };
    store_tile(0);
    __syncthreads();

    for (int kt = 0; kt < ktiles; kt++) {
        const int buf = kt & 1;
        if (kt + 1 < ktiles) {
            const float* Agn = Ag + (size_t)(kt + 1) * GBK;
            const float* Bgn = Bg + (size_t)(kt + 1) * GBK;
#pragma unroll
            for (int i = 0; i < 4; i++) ra[i] = *(const float4*)(Agn + (size_t)(i * 32) * K);
#pragma unroll
            for (int i = 0; i < 2; i++) rb[i] = *(const float4*)(Bgn + (size_t)(i * 32) * K);
        }
        const uint32_t* Ab = As + buf * GBM * ALD;
        const uint32_t* Bb = Bs + buf * GBN * ALD;
#pragma unroll
        for (int ks = 0; ks < 4; ks++) {
            uint32_t a[2][4], bfr[4][2];
#pragma unroll
            for (int mt = 0; mt < 2; mt++) {
                const uint32_t* ap = Ab + (wm + mt * 16 + g) * ALD + ks * 8 + c;
                a[mt][0] = ap[0];
                a[mt][1] = ap[8 * ALD];
                a[mt][2] = ap[4];
                a[mt][3] = ap[8 * ALD + 4];
            }
#pragma unroll
            for (int nt = 0; nt < 4; nt++) {
                const uint32_t* bp = Bb + (wn + nt * 8 + g) * ALD + ks * 8 + c;
                bfr[nt][0] = bp[0];
                bfr[nt][1] = bp[4];
            }
#pragma unroll
            for (int mt = 0; mt < 2; mt++)
#pragma unroll
                for (int nt = 0; nt < 4; nt++)
                    mma_tf32(acc[mt][nt], a[mt][0], a[mt][1], a[mt][2], a[mt][3],
                             bfr[nt][0], bfr[nt][1]);
        }
        if (kt + 1 < ktiles) {
            store_tile(buf ^ 1);
            __syncthreads();
        }
    }

#pragma unroll
    for (int mt = 0; mt < 2; mt++) {
        const int row0 = bm + wm + mt * 16 + g;
#pragma unroll
        for (int nt = 0; nt < 4; nt++) {
            const int col = bn + wn + nt * 8 + 2 * c;
            float b0 = 0.f, b1 = 0.f;
            if (bias) { b0 = bias[col]; b1 = bias[col + 1]; }
            float2 r0 = make_float2(acc[mt][nt][0] + b0, acc[mt][nt][1] + b1);
            float2 r1 = make_float2(acc[mt][nt][2] + b0, acc[mt][nt][3] + b1);
            if (cvt) {
                r0.x = __uint_as_float(f2tf(r0.x)); r0.y = __uint_as_float(f2tf(r0.y));
                r1.x = __uint_as_float(f2tf(r1.x)); r1.y = __uint_as_float(f2tf(r1.y));
            }
            *(float2*)(C + (size_t)row0 * N + col)       = r0;
            *(float2*)(C + (size_t)(row0 + 8) * N + col) = r1;
        }
    }
}

// ---------------------------------------------------------------------------
// Flash attention v6: v5 + QK k-split accumulators (break mma RAW chains) +
// head-group launches (4 heads per launch -> flash occupies launch slots 3-6
// so ncu -s 5 lands on it regardless of harness prelude launches).
// Warp (W = w&3, half = w>>2): q-rows 16W.., D-cols 64*half.. ; QK^T split
// along KT cols between halves; P via smem; no-max softmax (additive lsum).
// ---------------------------------------------------------------------------
#define QT   64
#define KT   32
#define QLD  132
#define KLD  132
#define VLD  136
#define PLD  36
#define QF    (QT*QLD)               // 8448
#define STG_F (KT*KLD + KT*VLD)      // 8576
#define VOFFS (KT*KLD)
#define PBASE (QF + 2*STG_F)         // 25600
#define LBASE (PBASE + QT*PLD)       // 27904
#define FLASH_SMEM ((LBASE + 2*QT) * 4)  // 112128 B

__global__ __launch_bounds__(256, 2)
void flash_attn(const float* __restrict__ Qg, const float* __restrict__ Kg,
                const float* __restrict__ Vg, float* __restrict__ Og, int h0) {
    const int qb = gridDim.x - 1 - blockIdx.x;   // heavy tiles first
    const int h  = h0 + blockIdx.y;
    const int b  = blockIdx.z;

    extern __shared__ uint32_t sm[];
    const uint32_t smem_u = (uint32_t)__cvta_generic_to_shared(sm);

    const int tid  = threadIdx.x;
    const int lane = tid & 31;
    const int w    = tid >> 5;
    const int g    = lane >> 2;
    const int c    = lane & 3;
    const int W    = w & 3;        // q-row block (16 rows)
    const int half = w >> 2;       // D-half / KT-col-half

    const size_t bh_off = ((size_t)b * SEQ) * EMB + (size_t)h * HDIM;

    // ---- Q tile -> smem (once) ----
    {
        const float* src = Qg + bh_off + (size_t)qb * QT * EMB;
#pragma unroll
        for (int i = 0; i < 8; i++) {
            const int idx = tid + i * 256;
            const int r   = idx >> 5;
            const int c4  = (idx & 31) << 2;
            cpa16(smem_u + (r * QLD + c4) * 4, src + (size_t)r * EMB + c4);
        }
        cpa_commit();
    }

    auto loadKV = [&](int t2) {
        const uint32_t base = smem_u + (QF + (t2 & 1) * STG_F) * 4;
        const float* kp = Kg + bh_off + (size_t)t2 * KT * EMB;
        const float* vp = Vg + bh_off + (size_t)t2 * KT * EMB;
#pragma unroll
        for (int i = 0; i < 4; i++) {
            const int idx = tid + i * 256;
            const int r   = idx >> 5;
            const int c4  = (idx & 31) << 2;
            cpa16(base + (r * KLD + c4) * 4, kp + (size_t)r * EMB + c4);
            cpa16(base + (VOFFS + r * VLD + c4) * 4, vp + (size_t)r * EMB + c4);
        }
        cpa_commit();
    };

    loadKV(0);

    float oacc[8][4];
#pragma unroll
    for (int i = 0; i < 8; i++)
#pragma unroll
        for (int j = 0; j < 4; j++) oacc[i][j] = 0.f;

    float lsum0 = 0.f, lsum1 = 0.f;
    const float sc2 = 0.08838834764831843f * 1.4426950408889634f; // log2e/sqrt(128)

    const int nkb   = 2 * qb + 2;
    const int kbmax = 2 * qb + (W >= 2 ? 1 : 0);
    const int row0  = qb * QT + W * 16 + g;
    const int row1  = row0 + 8;

    for (int t = 0; t < nkb; t++) {
        cpa_wait0();
        __syncthreads();
        if (t + 1 < nkb) loadKV(t + 1);

        const uint32_t* Kb = sm + QF + (t & 1) * STG_F;
        const uint32_t* Vb = Kb + VOFFS;
        const bool active = (t <= kbmax);

        if (active) {
            // ---- S half: 16 q-rows x 16 k-cols, 2-way k-split accumulators
            //      (4 independent RAW chains instead of 2) ----
            float sacc[2][2][4];   // [ksplit][nt][frag]
#pragma unroll
            for (int s = 0; s < 2; s++)
#pragma unroll
                for (int nt = 0; nt < 2; nt++)
#pragma unroll
                    for (int j = 0; j < 4; j++) sacc[s][nt][j] = 0.f;

#pragma unroll
            for (int ks = 0; ks < 8; ks++) {
                const uint32_t* ap0 = sm + (W * 16 + g) * QLD + ks * 8 + c;
                const uint32_t* ap1 = ap0 + 64;            // ks+8
                const uint32_t a00 = ap0[0], a01 = ap0[8 * QLD];
                const uint32_t a02 = ap0[4], a03 = ap0[8 * QLD + 4];
                const uint32_t a10 = ap1[0], a11 = ap1[8 * QLD];
                const uint32_t a12 = ap1[4], a13 = ap1[8 * QLD + 4];
#pragma unroll
                for (int nt = 0; nt < 2; nt++) {
                    const uint32_t* bp0 = Kb + (half * 16 + nt * 8 + g) * KLD + ks * 8 + c;
                    const uint32_t* bp1 = bp0 + 64;        // ks+8
                    mma_tf32(sacc[0][nt], a00, a01, a02, a03, bp0[0], bp0[4]);
                    mma_tf32(sacc[1][nt], a10, a11, a12, a13, bp1[0], bp1[4]);
                }
            }

            // ---- softmax numerator + write P half to smem ----
            const bool maskit = (t == kbmax);
            const int colbase = t * KT + half * 16 + 2 * c;
            uint32_t* Pw = sm + PBASE;
#pragma unroll
            for (int nt = 0; nt < 2; nt++) {
                float s0 = (sacc[0][nt][0] + sacc[1][nt][0]) * sc2;
                float s1 = (sacc[0][nt][1] + sacc[1][nt][1]) * sc2;
                float s2 = (sacc[0][nt][2] + sacc[1][nt][2]) * sc2;
                float s3 = (sacc[0][nt][3] + sacc[1][nt][3]) * sc2;
                if (maskit) {
                    const int c0 = colbase + nt * 8, c1 = c0 + 1;
                    if (c0 > row0) s0 = -126.f;
                    if (c1 > row0) s1 = -126.f;
                    if (c0 > row1) s2 = -126.f;
                    if (c1 > row1) s3 = -126.f;
                }
                const float p0 = ex2f(s0), p1 = ex2f(s1);
                const float p2 = ex2f(s2), p3 = ex2f(s3);
                lsum0 += p0 + p1;
                lsum1 += p2 + p3;
                const int lc = half * 16 + nt * 8 + 2 * c;
                *(uint2*)(Pw + (W * 16 + g) * PLD + lc)     = make_uint2(f2tf(p0), f2tf(p1));
                *(uint2*)(Pw + (W * 16 + g + 8) * PLD + lc) = make_uint2(f2tf(p2), f2tf(p3));
            }
        }

        __syncthreads();           // P exchange between halves

        if (active) {
            // ---- O += P V : full KT=32, own 64 D-cols ----
            const uint32_t* Pr = sm + PBASE;
#pragma unroll
            for (int ks = 0; ks < 4; ks++) {
                const uint32_t* ap = Pr + (W * 16 + g) * PLD + ks * 8 + c;
                const uint32_t a0 = ap[0], a1 = ap[8 * PLD];
                const uint32_t a2 = ap[4], a3 = ap[8 * PLD + 4];
#pragma unroll
                for (int nt = 0; nt < 8; nt++) {
                    const uint32_t* bp = Vb + (ks * 8 + c) * VLD + half * 64 + nt * 8 + g;
                    mma_tf32(oacc[nt], a0, a1, a2, a3, bp[0], bp[4 * VLD]);
                }
            }
        }
    }

    // ---- merge lsum halves (additive), normalize, store own D-half ----
#pragma unroll
    for (int msk = 1; msk < 4; msk <<= 1) {
        lsum0 += __shfl_xor_sync(0xffffffffu, lsum0, msk);
        lsum1 += __shfl_xor_sync(0xffffffffu, lsum1, msk);
    }
    float* fsm = (float*)sm;
    if (c == 0) {
        fsm[LBASE + (W * 16 + g) * 2 + half]     = lsum0;
        fsm[LBASE + (W * 16 + g + 8) * 2 + half] = lsum1;
    }
    __syncthreads();
    const float inv0 = 1.f / (fsm[LBASE + (W * 16 + g) * 2] +
                              fsm[LBASE + (W * 16 + g) * 2 + 1]);
    const float inv1 = 1.f / (fsm[LBASE + (W * 16 + g + 8) * 2] +
                              fsm[LBASE + (W * 16 + g + 8) * 2 + 1]);

    float* Obase = Og + bh_off + ((size_t)qb * QT + W * 16) * EMB;
#pragma unroll
    for (int nt = 0; nt < 8; nt++) {
        const int col = half * 64 + nt * 8 + 2 * c;
        *(float2*)(Obase + (size_t)g * EMB + col) =
            make_float2(oacc[nt][0] * inv0, oacc[nt][1] * inv0);
        *(float2*)(Obase + (size_t)(g + 8) * EMB + col) =
            make_float2(oacc[nt][2] * inv1, oacc[nt][3] * inv1);
    }
}

// ---------------------------------------------------------------------------
// Launch. Raw launch order: q(0), lat(1), kv-fused(2), flash x4 (3..6), out(7).
// Flash occupies indexes 3-6 so ncu -s 5 -c 1 hits flash for any harness
// prelude of 0..2 internal launches.
// ---------------------------------------------------------------------------
extern "C" void kernel_launch(void* const* d_in, const int* in_sizes, int n_in,
                              void* d_out, int out_size) {
    (void)in_sizes; (void)n_in; (void)out_size;
    const float* x      = (const float*)d_in[0];
    const float* w_q    = (const float*)d_in[1];
    const float* w_down = (const float*)d_in[2];
    const float* w_up_k = (const float*)d_in[3];
    const float* w_up_v = (const float*)d_in[4];
    const float* w_out  = (const float*)d_in[5];
    const float* b_out  = (const float*)d_in[6];
    float* out = (float*)d_out;

    void *pq, *plat, *pk, *pv, *pctx;
    cudaGetSymbolAddress(&pq,   g_q);
    cudaGetSymbolAddress(&plat, g_lat);
    cudaGetSymbolAddress(&pk,   g_k);
    cudaGetSymbolAddress(&pv,   g_v);
    cudaGetSymbolAddress(&pctx, g_ctx);

    const int GEMM_SMEM = (2 * GBM * ALD + 2 * GBN * ALD) * 4;   // 55296 B
    cudaFuncSetAttribute(gemm_tf32_nt, cudaFuncAttributeMaxDynamicSharedMemorySize, GEMM_SMEM);
    cudaFuncSetAttribute(flash_attn,  cudaFuncAttributeMaxDynamicSharedMemorySize, FLASH_SMEM);

    // 0: q = x @ w_q^T (tf32-rounded)
    gemm_tf32_nt<<<dim3(EMB / GBN, MTOT / GBM, 1), 256, GEMM_SMEM>>>(
        x, w_q, nullptr, nullptr, (float*)pq, nullptr, MTOT, EMB, EMB, 1);
    // 1: latent = x @ w_down^T (fp32)
    gemm_tf32_nt<<<dim3(LAT / GBN, MTOT / GBM, 1), 256, GEMM_SMEM>>>(
        x, w_down, nullptr, nullptr, (float*)plat, nullptr, MTOT, LAT, EMB, 0);
    // 2: k,v = latent @ w_up_{k,v}^T (fused via grid.z, tf32-rounded)
    gemm_tf32_nt<<<dim3(EMB / GBN, MTOT / GBM, 2), 256, GEMM_SMEM>>>(
        (const float*)plat, w_up_k, w_up_v, nullptr, (float*)pk, (float*)pv,
        MTOT, EMB, LAT, 1);
    // 3-6: causal attention, 4 heads per launch
    for (int h0 = 0; h0 < NHEAD; h0 += 4)
        flash_attn<<<dim3(SEQ / QT, 4, BATCH), 256, FLASH_SMEM>>>(
            (const float*)pq, (const float*)pk, (const float*)pv, (float*)pctx, h0);
    // 7: out = ctx @ w_out^T + b_out
    gemm_tf32_nt<<<dim3(EMB / GBN, MTOT / GBM, 1), 256, GEMM_SMEM>>>(
        (const float*)pctx, w_out, nullptr, b_out, out, nullptr, MTOT, EMB, EMB, 0);
}

// round 8
// speedup vs baseline: 1.2804x; 1.2804x over previous
#include <cuda_runtime.h>
#include <cstdint>
#include <cstddef>

// ---------------------------------------------------------------------------
// MultiHeadLatentAttention: x->q, x->latent, latent->k,v, causal MHA, out proj
// B=2 S=2048 EMB=2048 H=16 D=128 LATENT=512, fp32 in/out, tf32 MMA internally.
// ---------------------------------------------------------------------------

#define EMB   2048
#define BATCH 2
#define SEQ   2048
#define NHEAD 16
#define HDIM  128
#define LAT   512
#define MTOT  (BATCH*SEQ)   // 4096

__device__ float g_q  [(size_t)MTOT*EMB];
__device__ float g_lat[(size_t)MTOT*LAT];
__device__ float g_k  [(size_t)MTOT*EMB];
__device__ float g_v  [(size_t)MTOT*EMB];
__device__ float g_ctx[(size_t)MTOT*EMB];

__device__ __forceinline__ uint32_t f2tf(float f) {
    uint32_t u;
    asm("cvt.rna.tf32.f32 %0, %1;" : "=r"(u) : "f"(f));
    return u;
}

__device__ __forceinline__ float ex2f(float x) {
    float r;
    asm("ex2.approx.ftz.f32 %0, %1;" : "=f"(r) : "f"(x));
    return r;
}

__device__ __forceinline__ void mma_tf32(float d[4],
                                         uint32_t a0, uint32_t a1, uint32_t a2, uint32_t a3,
                                         uint32_t b0, uint32_t b1) {
    asm volatile(
        "mma.sync.aligned.m16n8k8.row.col.f32.tf32.tf32.f32 "
        "{%0,%1,%2,%3}, {%4,%5,%6,%7}, {%8,%9}, {%0,%1,%2,%3};"
        : "+f"(d[0]), "+f"(d[1]), "+f"(d[2]), "+f"(d[3])
        : "r"(a0), "r"(a1), "r"(a2), "r"(a3), "r"(b0), "r"(b1));
}

__device__ __forceinline__ void cpa16(uint32_t dst, const void* src) {
    asm volatile("cp.async.cg.shared.global [%0], [%1], 16;" :: "r"(dst), "l"(src));
}
__device__ __forceinline__ void cpa_commit() {
    asm volatile("cp.async.commit_group;" ::: "memory");
}
__device__ __forceinline__ void cpa_wait0() {
    asm volatile("cp.async.wait_group 0;" ::: "memory");
}

// ---------------------------------------------------------------------------
// GEMM: C[M,N] = A[M,K] * B[N,K]^T (+bias), tf32 MMA, fp32 accum.
// B2/C2 non-null: fused second GEMM selected by blockIdx.z (same A).
// ---------------------------------------------------------------------------
#define GBM 128
#define GBN 64
#define GBK 32
#define ALD 36

__global__ __launch_bounds__(256, 2)
void gemm_tf32_nt(const float* __restrict__ A, const float* __restrict__ B1,
                  const float* __restrict__ B2,
                  const float* __restrict__ bias, float* __restrict__ C1,
                  float* __restrict__ C2,
                  int M, int N, int K, int cvt) {
    extern __shared__ uint32_t sm[];
    uint32_t* As = sm;
    uint32_t* Bs = sm + 2 * GBM * ALD;

    const float* B = (blockIdx.z == 0) ? B1 : B2;
    float*       C = (blockIdx.z == 0) ? C1 : C2;

    const int tid  = threadIdx.x;
    const int lane = tid & 31;
    const int wid  = tid >> 5;
    const int g    = lane >> 2;
    const int c    = lane & 3;
    const int wm   = (wid >> 1) * 32;
    const int wn   = (wid & 1) * 32;

    const int bm = blockIdx.y * GBM;
    const int bn = blockIdx.x * GBN;

    float acc[2][4][4];
#pragma unroll
    for (int i = 0; i < 2; i++)
#pragma unroll
        for (int j = 0; j < 4; j++)
#pragma unroll
            for (int r = 0; r < 4; r++) acc[i][j][r] = 0.f;

    const int arow = tid >> 3;
    const int acol = (tid & 7) << 2;

    const float* Ag = A + (size_t)(bm + arow) * K + acol;
    const float* Bg = B + (size_t)(bn + arow) * K + acol;

    const int ktiles = K / GBK;
    float4 ra[4], rb[2];

#pragma unroll
    for (int i = 0; i < 4; i++) ra[i] = *(const float4*)(Ag + (size_t)(i * 32) * K);
#pragma unroll
    for (int i = 0; i < 2; i++) rb[i] = *(const float4*)(Bg + (size_t)(i * 32) * K);

    auto store_tile = [&](int buf) {
        uint32_t* Ab = As + buf * GBM * ALD;
        uint32_t* Bb = Bs + buf * GBN * ALD;
#pragma unroll
        for (int i = 0; i < 4; i++) {
            uint32_t* p = Ab + (arow + i * 32) * ALD + acol;
            p[0] = f2tf(ra[i].x); p[1] = f2tf(ra[i].y);
            p[2] = f2tf(ra[i].z); p[3] = f2tf(ra[i].w);
        }
#pragma unroll
        for (int i = 0; i < 2; i++) {
            uint32_t* p = Bb + (arow + i * 32) * ALD + acol;
            p[0] = f2tf(rb[i].x); p[1] = f2tf(rb[i].y);
            p[2] = f2tf(rb[i].z); p[3] = f2tf(rb[i].w);
        }
    };
    store_tile(0);
    __syncthreads();

    for (int kt = 0; kt < ktiles; kt++) {
        const int buf = kt & 1;
        if (kt + 1 < ktiles) {
            const float* Agn = Ag + (size_t)(kt + 1) * GBK;
            const float* Bgn = Bg + (size_t)(kt + 1) * GBK;
#pragma unroll
            for (int i = 0; i < 4; i++) ra[i] = *(const float4*)(Agn + (size_t)(i * 32) * K);
#pragma unroll
            for (int i = 0; i < 2; i++) rb[i] = *(const float4*)(Bgn + (size_t)(i * 32) * K);
        }
        const uint32_t* Ab = As + buf * GBM * ALD;
        const uint32_t* Bb = Bs + buf * GBN * ALD;
#pragma unroll
        for (int ks = 0; ks < 4; ks++) {
            uint32_t a[2][4], bfr[4][2];
#pragma unroll
            for (int mt = 0; mt < 2; mt++) {
                const uint32_t* ap = Ab + (wm + mt * 16 + g) * ALD + ks * 8 + c;
                a[mt][0] = ap[0];
                a[mt][1] = ap[8 * ALD];
                a[mt][2] = ap[4];
                a[mt][3] = ap[8 * ALD + 4];
            }
#pragma unroll
            for (int nt = 0; nt < 4; nt++) {
                const uint32_t* bp = Bb + (wn + nt * 8 + g) * ALD + ks * 8 + c;
                bfr[nt][0] = bp[0];
                bfr[nt][1] = bp[4];
            }
#pragma unroll
            for (int mt = 0; mt < 2; mt++)
#pragma unroll
                for (int nt = 0; nt < 4; nt++)
                    mma_tf32(acc[mt][nt], a[mt][0], a[mt][1], a[mt][2], a[mt][3],
                             bfr[nt][0], bfr[nt][1]);
        }
        if (kt + 1 < ktiles) {
            store_tile(buf ^ 1);
            __syncthreads();
        }
    }

#pragma unroll
    for (int mt = 0; mt < 2; mt++) {
        const int row0 = bm + wm + mt * 16 + g;
#pragma unroll
        for (int nt = 0; nt < 4; nt++) {
            const int col = bn + wn + nt * 8 + 2 * c;
            float b0 = 0.f, b1 = 0.f;
            if (bias) { b0 = bias[col]; b1 = bias[col + 1]; }
            float2 r0 = make_float2(acc[mt][nt][0] + b0, acc[mt][nt][1] + b1);
            float2 r1 = make_float2(acc[mt][nt][2] + b0, acc[mt][nt][3] + b1);
            if (cvt) {
                r0.x = __uint_as_float(f2tf(r0.x)); r0.y = __uint_as_float(f2tf(r0.y));
                r1.x = __uint_as_float(f2tf(r1.x)); r1.y = __uint_as_float(f2tf(r1.y));
            }
            *(float2*)(C + (size_t)row0 * N + col)       = r0;
            *(float2*)(C + (size_t)(row0 + 8) * N + col) = r1;
        }
    }
}

// ---------------------------------------------------------------------------
// Flash attention v6 (body unchanged): QT=64, KT=32, 256 thr, 2 blocks/SM.
// Warp (W = w&3, half = w>>2): q-rows 16W.., D-cols 64*half.. ; QK^T split
// along KT cols between halves (2-way k-split accumulators = 4 RAW chains);
// P via smem; no-max softmax (additive lsum). SINGLE full launch this round.
// ---------------------------------------------------------------------------
#define QT   64
#define KT   32
#define QLD  132
#define KLD  132
#define VLD  136
#define PLD  36
#define QF    (QT*QLD)               // 8448
#define STG_F (KT*KLD + KT*VLD)      // 8576
#define VOFFS (KT*KLD)
#define PBASE (QF + 2*STG_F)         // 25600
#define LBASE (PBASE + QT*PLD)       // 27904
#define FLASH_SMEM ((LBASE + 2*QT) * 4)  // 112128 B

__global__ __launch_bounds__(256, 2)
void flash_attn(const float* __restrict__ Qg, const float* __restrict__ Kg,
                const float* __restrict__ Vg, float* __restrict__ Og, int h0) {
    const int qb = gridDim.x - 1 - blockIdx.x;   // heavy tiles first
    const int h  = h0 + blockIdx.y;
    const int b  = blockIdx.z;

    extern __shared__ uint32_t sm[];
    const uint32_t smem_u = (uint32_t)__cvta_generic_to_shared(sm);

    const int tid  = threadIdx.x;
    const int lane = tid & 31;
    const int w    = tid >> 5;
    const int g    = lane >> 2;
    const int c    = lane & 3;
    const int W    = w & 3;        // q-row block (16 rows)
    const int half = w >> 2;       // D-half / KT-col-half

    const size_t bh_off = ((size_t)b * SEQ) * EMB + (size_t)h * HDIM;

    // ---- Q tile -> smem (once) ----
    {
        const float* src = Qg + bh_off + (size_t)qb * QT * EMB;
#pragma unroll
        for (int i = 0; i < 8; i++) {
            const int idx = tid + i * 256;
            const int r   = idx >> 5;
            const int c4  = (idx & 31) << 2;
            cpa16(smem_u + (r * QLD + c4) * 4, src + (size_t)r * EMB + c4);
        }
        cpa_commit();
    }

    auto loadKV = [&](int t2) {
        const uint32_t base = smem_u + (QF + (t2 & 1) * STG_F) * 4;
        const float* kp = Kg + bh_off + (size_t)t2 * KT * EMB;
        const float* vp = Vg + bh_off + (size_t)t2 * KT * EMB;
#pragma unroll
        for (int i = 0; i < 4; i++) {
            const int idx = tid + i * 256;
            const int r   = idx >> 5;
            const int c4  = (idx & 31) << 2;
            cpa16(base + (r * KLD + c4) * 4, kp + (size_t)r * EMB + c4);
            cpa16(base + (VOFFS + r * VLD + c4) * 4, vp + (size_t)r * EMB + c4);
        }
        cpa_commit();
    };

    loadKV(0);

    float oacc[8][4];
#pragma unroll
    for (int i = 0; i < 8; i++)
#pragma unroll
        for (int j = 0; j < 4; j++) oacc[i][j] = 0.f;

    float lsum0 = 0.f, lsum1 = 0.f;
    const float sc2 = 0.08838834764831843f * 1.4426950408889634f; // log2e/sqrt(128)

    const int nkb   = 2 * qb + 2;
    const int kbmax = 2 * qb + (W >= 2 ? 1 : 0);
    const int row0  = qb * QT + W * 16 + g;
    const int row1  = row0 + 8;

    for (int t = 0; t < nkb; t++) {
        cpa_wait0();
        __syncthreads();
        if (t + 1 < nkb) loadKV(t + 1);

        const uint32_t* Kb = sm + QF + (t & 1) * STG_F;
        const uint32_t* Vb = Kb + VOFFS;
        const bool active = (t <= kbmax);

        if (active) {
            // ---- S half: 16 q-rows x 16 k-cols, 2-way k-split accumulators ----
            float sacc[2][2][4];   // [ksplit][nt][frag]
#pragma unroll
            for (int s = 0; s < 2; s++)
#pragma unroll
                for (int nt = 0; nt < 2; nt++)
#pragma unroll
                    for (int j = 0; j < 4; j++) sacc[s][nt][j] = 0.f;

#pragma unroll
            for (int ks = 0; ks < 8; ks++) {
                const uint32_t* ap0 = sm + (W * 16 + g) * QLD + ks * 8 + c;
                const uint32_t* ap1 = ap0 + 64;            // ks+8
                const uint32_t a00 = ap0[0], a01 = ap0[8 * QLD];
                const uint32_t a02 = ap0[4], a03 = ap0[8 * QLD + 4];
                const uint32_t a10 = ap1[0], a11 = ap1[8 * QLD];
                const uint32_t a12 = ap1[4], a13 = ap1[8 * QLD + 4];
#pragma unroll
                for (int nt = 0; nt < 2; nt++) {
                    const uint32_t* bp0 = Kb + (half * 16 + nt * 8 + g) * KLD + ks * 8 + c;
                    const uint32_t* bp1 = bp0 + 64;        // ks+8
                    mma_tf32(sacc[0][nt], a00, a01, a02, a03, bp0[0], bp0[4]);
                    mma_tf32(sacc[1][nt], a10, a11, a12, a13, bp1[0], bp1[4]);
                }
            }

            // ---- softmax numerator + write P half to smem ----
            const bool maskit = (t == kbmax);
            const int colbase = t * KT + half * 16 + 2 * c;
            uint32_t* Pw = sm + PBASE;
#pragma unroll
            for (int nt = 0; nt < 2; nt++) {
                float s0 = (sacc[0][nt][0] + sacc[1][nt][0]) * sc2;
                float s1 = (sacc[0][nt][1] + sacc[1][nt][1]) * sc2;
                float s2 = (sacc[0][nt][2] + sacc[1][nt][2]) * sc2;
                float s3 = (sacc[0][nt][3] + sacc[1][nt][3]) * sc2;
                if (maskit) {
                    const int c0 = colbase + nt * 8, c1 = c0 + 1;
                    if (c0 > row0) s0 = -126.f;
                    if (c1 > row0) s1 = -126.f;
                    if (c0 > row1) s2 = -126.f;
                    if (c1 > row1) s3 = -126.f;
                }
                const float p0 = ex2f(s0), p1 = ex2f(s1);
                const float p2 = ex2f(s2), p3 = ex2f(s3);
                lsum0 += p0 + p1;
                lsum1 += p2 + p3;
                const int lc = half * 16 + nt * 8 + 2 * c;
                *(uint2*)(Pw + (W * 16 + g) * PLD + lc)     = make_uint2(f2tf(p0), f2tf(p1));
                *(uint2*)(Pw + (W * 16 + g + 8) * PLD + lc) = make_uint2(f2tf(p2), f2tf(p3));
            }
        }

        __syncthreads();           // P exchange between halves

        if (active) {
            // ---- O += P V : full KT=32, own 64 D-cols ----
            const uint32_t* Pr = sm + PBASE;
#pragma unroll
            for (int ks = 0; ks < 4; ks++) {
                const uint32_t* ap = Pr + (W * 16 + g) * PLD + ks * 8 + c;
                const uint32_t a0 = ap[0], a1 = ap[8 * PLD];
                const uint32_t a2 = ap[4], a3 = ap[8 * PLD + 4];
#pragma unroll
                for (int nt = 0; nt < 8; nt++) {
                    const uint32_t* bp = Vb + (ks * 8 + c) * VLD + half * 64 + nt * 8 + g;
                    mma_tf32(oacc[nt], a0, a1, a2, a3, bp[0], bp[4 * VLD]);
                }
            }
        }
    }

    // ---- merge lsum halves (additive), normalize, store own D-half ----
#pragma unroll
    for (int msk = 1; msk < 4; msk <<= 1) {
        lsum0 += __shfl_xor_sync(0xffffffffu, lsum0, msk);
        lsum1 += __shfl_xor_sync(0xffffffffu, lsum1, msk);
    }
    float* fsm = (float*)sm;
    if (c == 0) {
        fsm[LBASE + (W * 16 + g) * 2 + half]     = lsum0;
        fsm[LBASE + (W * 16 + g + 8) * 2 + half] = lsum1;
    }
    __syncthreads();
    const float inv0 = 1.f / (fsm[LBASE + (W * 16 + g) * 2] +
                              fsm[LBASE + (W * 16 + g) * 2 + 1]);
    const float inv1 = 1.f / (fsm[LBASE + (W * 16 + g + 8) * 2] +
                              fsm[LBASE + (W * 16 + g + 8) * 2 + 1]);

    float* Obase = Og + bh_off + ((size_t)qb * QT + W * 16) * EMB;
#pragma unroll
    for (int nt = 0; nt < 8; nt++) {
        const int col = half * 64 + nt * 8 + 2 * c;
        *(float2*)(Obase + (size_t)g * EMB + col) =
            make_float2(oacc[nt][0] * inv0, oacc[nt][1] * inv0);
        *(float2*)(Obase + (size_t)(g + 8) * EMB + col) =
            make_float2(oacc[nt][2] * inv1, oacc[nt][3] * inv1);
    }
}

// ---------------------------------------------------------------------------
// Launch. App order: q(0), lat(1), kv-fused(2), flash(3), out(4).
// With the confirmed 2-launch harness prelude, ncu -s 5 -c 1 lands on flash.
// ---------------------------------------------------------------------------
extern "C" void kernel_launch(void* const* d_in, const int* in_sizes, int n_in,
                              void* d_out, int out_size) {
    (void)in_sizes; (void)n_in; (void)out_size;
    const float* x      = (const float*)d_in[0];
    const float* w_q    = (const float*)d_in[1];
    const float* w_down = (const float*)d_in[2];
    const float* w_up_k = (const float*)d_in[3];
    const float* w_up_v = (const float*)d_in[4];
    const float* w_out  = (const float*)d_in[5];
    const float* b_out  = (const float*)d_in[6];
    float* out = (float*)d_out;

    void *pq, *plat, *pk, *pv, *pctx;
    cudaGetSymbolAddress(&pq,   g_q);
    cudaGetSymbolAddress(&plat, g_lat);
    cudaGetSymbolAddress(&pk,   g_k);
    cudaGetSymbolAddress(&pv,   g_v);
    cudaGetSymbolAddress(&pctx, g_ctx);

    const int GEMM_SMEM = (2 * GBM * ALD + 2 * GBN * ALD) * 4;   // 55296 B
    cudaFuncSetAttribute(gemm_tf32_nt, cudaFuncAttributeMaxDynamicSharedMemorySize, GEMM_SMEM);
    cudaFuncSetAttribute(flash_attn,  cudaFuncAttributeMaxDynamicSharedMemorySize, FLASH_SMEM);

    // 0: q = x @ w_q^T (tf32-rounded)
    gemm_tf32_nt<<<dim3(EMB / GBN, MTOT / GBM, 1), 256, GEMM_SMEM>>>(
        x, w_q, nullptr, nullptr, (float*)pq, nullptr, MTOT, EMB, EMB, 1);
    // 1: latent = x @ w_down^T (fp32)
    gemm_tf32_nt<<<dim3(LAT / GBN, MTOT / GBM, 1), 256, GEMM_SMEM>>>(
        x, w_down, nullptr, nullptr, (float*)plat, nullptr, MTOT, LAT, EMB, 0);
    // 2: k,v = latent @ w_up_{k,v}^T (fused via grid.z, tf32-rounded)
    gemm_tf32_nt<<<dim3(EMB / GBN, MTOT / GBM, 2), 256, GEMM_SMEM>>>(
        (const float*)plat, w_up_k, w_up_v, nullptr, (float*)pk, (float*)pv,
        MTOT, EMB, LAT, 1);
    // 3: causal attention — SINGLE launch, all heads (1024 blocks, balanced)
    flash_attn<<<dim3(SEQ / QT, NHEAD, BATCH), 256, FLASH_SMEM>>>(
        (const float*)pq, (const float*)pk, (const float*)pv, (float*)pctx, 0);
    // 4: out = ctx @ w_out^T + b_out
    gemm_tf32_nt<<<dim3(EMB / GBN, MTOT / GBM, 1), 256, GEMM_SMEM>>>(
        (const float*)pctx, w_out, nullptr, b_out, out, nullptr, MTOT, EMB, EMB, 0);
}

// round 9
// speedup vs baseline: 1.4181x; 1.1075x over previous
#include <cuda_runtime.h>
#include <cstdint>
#include <cstddef>

#define EMB   2048
#define BATCH 2
#define SEQ   2048
#define NHEAD 16
#define HDIM  128
#define LAT   512
#define MTOT  (BATCH*SEQ)   // 4096

__device__ float g_q  [(size_t)MTOT*EMB];
__device__ float g_lat[(size_t)MTOT*LAT];
__device__ float g_k  [(size_t)MTOT*EMB];
__device__ float g_v  [(size_t)MTOT*EMB];
__device__ float g_ctx[(size_t)MTOT*EMB];

__device__ __forceinline__ uint32_t f2tf(float f) {
    uint32_t u;
    asm("cvt.rna.tf32.f32 %0, %1;" : "=r"(u) : "f"(f));
    return u;
}
__device__ __forceinline__ float ex2f(float x) {
    float r;
    asm("ex2.approx.ftz.f32 %0, %1;" : "=f"(r) : "f"(x));
    return r;
}
__device__ __forceinline__ void mma_tf32(float d[4],
                                         uint32_t a0, uint32_t a1, uint32_t a2, uint32_t a3,
                                         uint32_t b0, uint32_t b1) {
    asm volatile(
        "mma.sync.aligned.m16n8k8.row.col.f32.tf32.tf32.f32 "
        "{%0,%1,%2,%3}, {%4,%5,%6,%7}, {%8,%9}, {%0,%1,%2,%3};"
        : "+f"(d[0]), "+f"(d[1]), "+f"(d[2]), "+f"(d[3])
        : "r"(a0), "r"(a1), "r"(a2), "r"(a3), "r"(b0), "r"(b1));
}
__device__ __forceinline__ void ldsm4(uint32_t r[4], uint32_t addr) {
    asm volatile("ldmatrix.sync.aligned.m8n8.x4.shared.b16 {%0,%1,%2,%3}, [%4];"
        : "=r"(r[0]), "=r"(r[1]), "=r"(r[2]), "=r"(r[3]) : "r"(addr));
}
__device__ __forceinline__ void cpa16(uint32_t dst, const void* src) {
    asm volatile("cp.async.cg.shared.global [%0], [%1], 16;" :: "r"(dst), "l"(src));
}
__device__ __forceinline__ void cpa_commit() {
    asm volatile("cp.async.commit_group;" ::: "memory");
}
__device__ __forceinline__ void cpa_wait0() {
    asm volatile("cp.async.wait_group 0;" ::: "memory");
}

// ---------------------------------------------------------------------------
// GEMM v2: C[M,N] = A[M,K]*B[N,K]^T (+bias). Block 128x64, 128 thr, 4 warps,
// warp tile 64x32 (192 B/mma). Fragment loads via ldmatrix.x4 (6 LDSM per
// 16 mma, replacing 32 scalar LDS). B2/C2: fused 2nd GEMM via blockIdx.z.
// ---------------------------------------------------------------------------
#define GBM 128
#define GBN 64
#define GBK 32
#define ALD 36

__global__ __launch_bounds__(128, 3)
void gemm_tf32_nt(const float* __restrict__ A, const float* __restrict__ B1,
                  const float* __restrict__ B2,
                  const float* __restrict__ bias, float* __restrict__ C1,
                  float* __restrict__ C2,
                  int M, int N, int K, int cvt) {
    extern __shared__ uint32_t sm[];
    uint32_t* As = sm;                  // [2][128][36]
    uint32_t* Bs = sm + 2 * GBM * ALD;  // [2][64][36]
    const uint32_t smem_u = (uint32_t)__cvta_generic_to_shared(sm);

    const float* B = (blockIdx.z == 0) ? B1 : B2;
    float*       C = (blockIdx.z == 0) ? C1 : C2;

    const int tid  = threadIdx.x;
    const int lane = tid & 31;
    const int wid  = tid >> 5;
    const int g    = lane >> 2;
    const int c    = lane & 3;
    const int wm   = (wid >> 1) * 64;
    const int wn   = (wid & 1) * 32;

    // ldmatrix per-lane address components (A: 16x8 frag, B: two 8x8 frags)
    const int aRow = (lane & 7) + ((lane >> 3) & 1) * 8;
    const int aK   = (lane >> 4) * 4;
    const int bN   = (lane & 7) + (lane >> 4) * 8;
    const int bK   = ((lane >> 3) & 1) * 4;

    const int bm = blockIdx.y * GBM;
    const int bn = blockIdx.x * GBN;

    float acc[4][4][4];
#pragma unroll
    for (int i = 0; i < 4; i++)
#pragma unroll
        for (int j = 0; j < 4; j++)
#pragma unroll
            for (int r = 0; r < 4; r++) acc[i][j][r] = 0.f;

    const int arow = tid >> 3;        // 0..15
    const int acol = (tid & 7) << 2;  // 0..28

    const float* Ag = A + (size_t)(bm + arow) * K + acol;
    const float* Bg = B + (size_t)(bn + arow) * K + acol;

    const int ktiles = K / GBK;
    float4 ra[8], rb[4];

#pragma unroll
    for (int i = 0; i < 8; i++) ra[i] = *(const float4*)(Ag + (size_t)(i * 16) * K);
#pragma unroll
    for (int i = 0; i < 4; i++) rb[i] = *(const float4*)(Bg + (size_t)(i * 16) * K);

    auto store_tile = [&](int buf) {
        uint32_t* Ab = As + buf * GBM * ALD;
        uint32_t* Bb = Bs + buf * GBN * ALD;
#pragma unroll
        for (int i = 0; i < 8; i++) {
            uint32_t* p = Ab + (arow + i * 16) * ALD + acol;
            p[0] = f2tf(ra[i].x); p[1] = f2tf(ra[i].y);
            p[2] = f2tf(ra[i].z); p[3] = f2tf(ra[i].w);
        }
#pragma unroll
        for (int i = 0; i < 4; i++) {
            uint32_t* p = Bb + (arow + i * 16) * ALD + acol;
            p[0] = f2tf(rb[i].x); p[1] = f2tf(rb[i].y);
            p[2] = f2tf(rb[i].z); p[3] = f2tf(rb[i].w);
        }
    };
    store_tile(0);
    __syncthreads();

    for (int kt = 0; kt < ktiles; kt++) {
        const int buf = kt & 1;
        if (kt + 1 < ktiles) {
            const float* Agn = Ag + (size_t)(kt + 1) * GBK;
            const float* Bgn = Bg + (size_t)(kt + 1) * GBK;
#pragma unroll
            for (int i = 0; i < 8; i++) ra[i] = *(const float4*)(Agn + (size_t)(i * 16) * K);
#pragma unroll
            for (int i = 0; i < 4; i++) rb[i] = *(const float4*)(Bgn + (size_t)(i * 16) * K);
        }
        const uint32_t Abase = smem_u + (buf * GBM * ALD) * 4;
        const uint32_t Bbase = smem_u + (2 * GBM * ALD + buf * GBN * ALD) * 4;
#pragma unroll
        for (int ks = 0; ks < 4; ks++) {
            uint32_t afr[4][4], bfr[4][2];
#pragma unroll
            for (int mt = 0; mt < 4; mt++)
                ldsm4(afr[mt], Abase + ((wm + mt * 16 + aRow) * ALD + ks * 8 + aK) * 4);
#pragma unroll
            for (int j = 0; j < 2; j++) {
                uint32_t r4[4];
                ldsm4(r4, Bbase + ((wn + j * 16 + bN) * ALD + ks * 8 + bK) * 4);
                bfr[2 * j][0]     = r4[0];
                bfr[2 * j][1]     = r4[1];
                bfr[2 * j + 1][0] = r4[2];
                bfr[2 * j + 1][1] = r4[3];
            }
#pragma unroll
            for (int mt = 0; mt < 4; mt++)
#pragma unroll
                for (int nt = 0; nt < 4; nt++)
                    mma_tf32(acc[mt][nt], afr[mt][0], afr[mt][1], afr[mt][2], afr[mt][3],
                             bfr[nt][0], bfr[nt][1]);
        }
        if (kt + 1 < ktiles) {
            store_tile(buf ^ 1);
            __syncthreads();
        }
    }

#pragma unroll
    for (int mt = 0; mt < 4; mt++) {
        const int row0 = bm + wm + mt * 16 + g;
#pragma unroll
        for (int nt = 0; nt < 4; nt++) {
            const int col = bn + wn + nt * 8 + 2 * c;
            float b0 = 0.f, b1 = 0.f;
            if (bias) { b0 = bias[col]; b1 = bias[col + 1]; }
            float2 r0 = make_float2(acc[mt][nt][0] + b0, acc[mt][nt][1] + b1);
            float2 r1 = make_float2(acc[mt][nt][2] + b0, acc[mt][nt][3] + b1);
            if (cvt) {
                r0.x = __uint_as_float(f2tf(r0.x)); r0.y = __uint_as_float(f2tf(r0.y));
                r1.x = __uint_as_float(f2tf(r1.x)); r1.y = __uint_as_float(f2tf(r1.y));
            }
            *(float2*)(C + (size_t)row0 * N + col)       = r0;
            *(float2*)(C + (size_t)(row0 + 8) * N + col) = r1;
        }
    }
}

// ---------------------------------------------------------------------------
// Flash attention v6 (UNCHANGED from R8, 363us measured): QT=64, KT=32,
// 256 thr, 2 blocks/SM, no-max softmax, P via smem, single launch.
// ---------------------------------------------------------------------------
#define QT   64
#define KT   32
#define QLD  132
#define KLD  132
#define VLD  136
#define PLD  36
#define QF    (QT*QLD)               // 8448
#define STG_F (KT*KLD + KT*VLD)      // 8576
#define VOFFS (KT*KLD)
#define PBASE (QF + 2*STG_F)         // 25600
#define LBASE (PBASE + QT*PLD)       // 27904
#define FLASH_SMEM ((LBASE + 2*QT) * 4)  // 112128 B

__global__ __launch_bounds__(256, 2)
void flash_attn(const float* __restrict__ Qg, const float* __restrict__ Kg,
                const float* __restrict__ Vg, float* __restrict__ Og, int h0) {
    const int qb = gridDim.x - 1 - blockIdx.x;   // heavy tiles first
    const int h  = h0 + blockIdx.y;
    const int b  = blockIdx.z;

    extern __shared__ uint32_t sm[];
    const uint32_t smem_u = (uint32_t)__cvta_generic_to_shared(sm);

    const int tid  = threadIdx.x;
    const int lane = tid & 31;
    const int w    = tid >> 5;
    const int g    = lane >> 2;
    const int c    = lane & 3;
    const int W    = w & 3;
    const int half = w >> 2;

    const size_t bh_off = ((size_t)b * SEQ) * EMB + (size_t)h * HDIM;

    {
        const float* src = Qg + bh_off + (size_t)qb * QT * EMB;
#pragma unroll
        for (int i = 0; i < 8; i++) {
            const int idx = tid + i * 256;
            const int r   = idx >> 5;
            const int c4  = (idx & 31) << 2;
            cpa16(smem_u + (r * QLD + c4) * 4, src + (size_t)r * EMB + c4);
        }
        cpa_commit();
    }

    auto loadKV = [&](int t2) {
        const uint32_t base = smem_u + (QF + (t2 & 1) * STG_F) * 4;
        const float* kp = Kg + bh_off + (size_t)t2 * KT * EMB;
        const float* vp = Vg + bh_off + (size_t)t2 * KT * EMB;
#pragma unroll
        for (int i = 0; i < 4; i++) {
            const int idx = tid + i * 256;
            const int r   = idx >> 5;
            const int c4  = (idx & 31) << 2;
            cpa16(base + (r * KLD + c4) * 4, kp + (size_t)r * EMB + c4);
            cpa16(base + (VOFFS + r * VLD + c4) * 4, vp + (size_t)r * EMB + c4);
        }
        cpa_commit();
    };

    loadKV(0);

    float oacc[8][4];
#pragma unroll
    for (int i = 0; i < 8; i++)
#pragma unroll
        for (int j = 0; j < 4; j++) oacc[i][j] = 0.f;

    float lsum0 = 0.f, lsum1 = 0.f;
    const float sc2 = 0.08838834764831843f * 1.4426950408889634f;

    const int nkb   = 2 * qb + 2;
    const int kbmax = 2 * qb + (W >= 2 ? 1 : 0);
    const int row0  = qb * QT + W * 16 + g;
    const int row1  = row0 + 8;

    for (int t = 0; t < nkb; t++) {
        cpa_wait0();
        __syncthreads();
        if (t + 1 < nkb) loadKV(t + 1);

        const uint32_t* Kb = sm + QF + (t & 1) * STG_F;
        const uint32_t* Vb = Kb + VOFFS;
        const bool active = (t <= kbmax);

        if (active) {
            float sacc[2][2][4];
#pragma unroll
            for (int s = 0; s < 2; s++)
#pragma unroll
                for (int nt = 0; nt < 2; nt++)
#pragma unroll
                    for (int j = 0; j < 4; j++) sacc[s][nt][j] = 0.f;

#pragma unroll
            for (int ks = 0; ks < 8; ks++) {
                const uint32_t* ap0 = sm + (W * 16 + g) * QLD + ks * 8 + c;
                const uint32_t* ap1 = ap0 + 64;
                const uint32_t a00 = ap0[0], a01 = ap0[8 * QLD];
                const uint32_t a02 = ap0[4], a03 = ap0[8 * QLD + 4];
                const uint32_t a10 = ap1[0], a11 = ap1[8 * QLD];
                const uint32_t a12 = ap1[4], a13 = ap1[8 * QLD + 4];
#pragma unroll
                for (int nt = 0; nt < 2; nt++) {
                    const uint32_t* bp0 = Kb + (half * 16 + nt * 8 + g) * KLD + ks * 8 + c;
                    const uint32_t* bp1 = bp0 + 64;
                    mma_tf32(sacc[0][nt], a00, a01, a02, a03, bp0[0], bp0[4]);
                    mma_tf32(sacc[1][nt], a10, a11, a12, a13, bp1[0], bp1[4]);
                }
            }

            const bool maskit = (t == kbmax);
            const int colbase = t * KT + half * 16 + 2 * c;
            uint32_t* Pw = sm + PBASE;
#pragma unroll
            for (int nt = 0; nt < 2; nt++) {
                float s0 = (sacc[0][nt][0] + sacc[1][nt][0]) * sc2;
                float s1 = (sacc[0][nt][1] + sacc[1][nt][1]) * sc2;
                float s2 = (sacc[0][nt][2] + sacc[1][nt][2]) * sc2;
                float s3 = (sacc[0][nt][3] + sacc[1][nt][3]) * sc2;
                if (maskit) {
                    const int c0 = colbase + nt * 8, c1 = c0 + 1;
                    if (c0 > row0) s0 = -126.f;
                    if (c1 > row0) s1 = -126.f;
                    if (c0 > row1) s2 = -126.f;
                    if (c1 > row1) s3 = -126.f;
                }
                const float p0 = ex2f(s0), p1 = ex2f(s1);
                const float p2 = ex2f(s2), p3 = ex2f(s3);
                lsum0 += p0 + p1;
                lsum1 += p2 + p3;
                const int lc = half * 16 + nt * 8 + 2 * c;
                *(uint2*)(Pw + (W * 16 + g) * PLD + lc)     = make_uint2(f2tf(p0), f2tf(p1));
                *(uint2*)(Pw + (W * 16 + g + 8) * PLD + lc) = make_uint2(f2tf(p2), f2tf(p3));
            }
        }

        __syncthreads();

        if (active) {
            const uint32_t* Pr = sm + PBASE;
#pragma unroll
            for (int ks = 0; ks < 4; ks++) {
                const uint32_t* ap = Pr + (W * 16 + g) * PLD + ks * 8 + c;
                const uint32_t a0 = ap[0], a1 = ap[8 * PLD];
                const uint32_t a2 = ap[4], a3 = ap[8 * PLD + 4];
#pragma unroll
                for (int nt = 0; nt < 8; nt++) {
                    const uint32_t* bp = Vb + (ks * 8 + c) * VLD + half * 64 + nt * 8 + g;
                    mma_tf32(oacc[nt], a0, a1, a2, a3, bp[0], bp[4 * VLD]);
                }
            }
        }
    }

#pragma unroll
    for (int msk = 1; msk < 4; msk <<= 1) {
        lsum0 += __shfl_xor_sync(0xffffffffu, lsum0, msk);
        lsum1 += __shfl_xor_sync(0xffffffffu, lsum1, msk);
    }
    float* fsm = (float*)sm;
    if (c == 0) {
        fsm[LBASE + (W * 16 + g) * 2 + half]     = lsum0;
        fsm[LBASE + (W * 16 + g + 8) * 2 + half] = lsum1;
    }
    __syncthreads();
    const float inv0 = 1.f / (fsm[LBASE + (W * 16 + g) * 2] +
                              fsm[LBASE + (W * 16 + g) * 2 + 1]);
    const float inv1 = 1.f / (fsm[LBASE + (W * 16 + g + 8) * 2] +
                              fsm[LBASE + (W * 16 + g + 8) * 2 + 1]);

    float* Obase = Og + bh_off + ((size_t)qb * QT + W * 16) * EMB;
#pragma unroll
    for (int nt = 0; nt < 8; nt++) {
        const int col = half * 64 + nt * 8 + 2 * c;
        *(float2*)(Obase + (size_t)g * EMB + col) =
            make_float2(oacc[nt][0] * inv0, oacc[nt][1] * inv0);
        *(float2*)(Obase + (size_t)(g + 8) * EMB + col) =
            make_float2(oacc[nt][2] * inv1, oacc[nt][3] * inv1);
    }
}

// ---------------------------------------------------------------------------
// Launch: q(0), lat(1), kv-fused(2), flash(3), out(4). ncu -s 5 -> flash.
// ---------------------------------------------------------------------------
extern "C" void kernel_launch(void* const* d_in, const int* in_sizes, int n_in,
                              void* d_out, int out_size) {
    (void)in_sizes; (void)n_in; (void)out_size;
    const float* x      = (const float*)d_in[0];
    const float* w_q    = (const float*)d_in[1];
    const float* w_down = (const float*)d_in[2];
    const float* w_up_k = (const float*)d_in[3];
    const float* w_up_v = (const float*)d_in[4];
    const float* w_out  = (const float*)d_in[5];
    const float* b_out  = (const float*)d_in[6];
    float* out = (float*)d_out;

    void *pq, *plat, *pk, *pv, *pctx;
    cudaGetSymbolAddress(&pq,   g_q);
    cudaGetSymbolAddress(&plat, g_lat);
    cudaGetSymbolAddress(&pk,   g_k);
    cudaGetSymbolAddress(&pv,   g_v);
    cudaGetSymbolAddress(&pctx, g_ctx);

    const int GEMM_SMEM = (2 * GBM * ALD + 2 * GBN * ALD) * 4;   // 55296 B
    cudaFuncSetAttribute(gemm_tf32_nt, cudaFuncAttributeMaxDynamicSharedMemorySize, GEMM_SMEM);
    cudaFuncSetAttribute(flash_attn,  cudaFuncAttributeMaxDynamicSharedMemorySize, FLASH_SMEM);

    // 0: q = x @ w_q^T (tf32-rounded)
    gemm_tf32_nt<<<dim3(EMB / GBN, MTOT / GBM, 1), 128, GEMM_SMEM>>>(
        x, w_q, nullptr, nullptr, (float*)pq, nullptr, MTOT, EMB, EMB, 1);
    // 1: latent = x @ w_down^T (fp32)
    gemm_tf32_nt<<<dim3(LAT / GBN, MTOT / GBM, 1), 128, GEMM_SMEM>>>(
        x, w_down, nullptr, nullptr, (float*)plat, nullptr, MTOT, LAT, EMB, 0);
    // 2: k,v = latent @ w_up_{k,v}^T (fused via grid.z, tf32-rounded)
    gemm_tf32_nt<<<dim3(EMB / GBN, MTOT / GBM, 2), 128, GEMM_SMEM>>>(
        (const float*)plat, w_up_k, w_up_v, nullptr, (float*)pk, (float*)pv,
        MTOT, EMB, LAT, 1);
    // 3: causal attention — single launch, all heads
    flash_attn<<<dim3(SEQ / QT, NHEAD, BATCH), 256, FLASH_SMEM>>>(
        (const float*)pq, (const float*)pk, (const float*)pv, (float*)pctx, 0);
    // 4: out = ctx @ w_out^T + b_out
    gemm_tf32_nt<<<dim3(EMB / GBN, MTOT / GBM, 1), 128, GEMM_SMEM>>>(
        (const float*)pctx, w_out, nullptr, b_out, out, nullptr, MTOT, EMB, EMB, 0);
}